// round 1
// baseline (speedup 1.0000x reference)
#include <cuda_runtime.h>
#include <cstdint>
#include <cstdio>

// ---------------- problem constants ----------------
#define BATCH   512
#define NT      8
#define NR      8
#define LD      256
#define LP      16
#define LDPC_N  4096            // 2*NT*LD
#define M_A     12288           // 3*LDPC_N
#define YYW     544             // 2*(LD+LP)
#define MAX_ROW_NNZ 64
#define MAX_COL_NNZ 160

#define TWO_SQ2 2.8284271247461903f
#define INV_SQ2 0.70710678118654752f

// ---------------- device scratch (no allocs allowed) ----------------
__device__ float g_vT [M_A    * BATCH];   // theta - z - lambda1, (i,b)
__device__ float g_zT [M_A    * BATCH];
__device__ float g_lT [M_A    * BATCH];
__device__ float g_zTn[M_A    * BATCH];
__device__ float g_lTn[M_A    * BATCH];
__device__ float g_FT [LDPC_N * BATCH];   // F transposed, (m,b)
__device__ float g_uT [LDPC_N * BATCH];   // u transposed, (j,b)
__device__ float g_XT [LDPC_N * BATCH];   // X transposed, ((r*256+l),b)
__device__ float g_X  [BATCH * LDPC_N];   // X in (b, 16, 256)

__device__ int g_csr_cols[M_A * MAX_ROW_NNZ];
__device__ int g_csr_cnt [M_A];
__device__ int g_csc_rows[LDPC_N * MAX_COL_NNZ];
__device__ int g_csc_cnt [LDPC_N];

// ---------------- P0: zero csc counters ----------------
__global__ void k_zero_cnt() {
    int j = blockIdx.x * blockDim.x + threadIdx.x;
    if (j < LDPC_N) g_csc_cnt[j] = 0;
}

// ---------------- P1: build CSR (ordered) + CSC (unordered) ----------------
__global__ void k_build(const float* __restrict__ A) {
    int warp = (blockIdx.x * blockDim.x + threadIdx.x) >> 5;
    int lane = threadIdx.x & 31;
    if (warp >= M_A) return;
    int i = warp;
    int cnt = 0;
    const size_t rowbase = (size_t)i * LDPC_N;
    for (int k0 = 0; k0 < LDPC_N; k0 += 32) {
        float v = A[rowbase + k0 + lane];
        unsigned m = __ballot_sync(0xffffffffu, v != 0.0f);
        if (v != 0.0f) {
            int pos = cnt + __popc(m & ((1u << lane) - 1u));
            if (pos < MAX_ROW_NNZ) g_csr_cols[i * MAX_ROW_NNZ + pos] = k0 + lane;
            int j = k0 + lane;
            int cp = atomicAdd(&g_csc_cnt[j], 1);
            if (cp < MAX_COL_NNZ) g_csc_rows[j * MAX_COL_NNZ + cp] = i;
        }
        cnt += __popc(m);
    }
    if (lane == 0) g_csr_cnt[i] = (cnt < MAX_ROW_NNZ) ? cnt : MAX_ROW_NNZ;
}

// ---------------- P2: sort each CSC column (determinism) ----------------
__global__ void k_sort_csc() {
    int w    = threadIdx.x >> 5;
    int lane = threadIdx.x & 31;
    int j    = blockIdx.x * 8 + w;
    if (j >= LDPC_N) return;
    __shared__ int sh[8][MAX_COL_NNZ];
    int n = g_csc_cnt[j];
    if (n > MAX_COL_NNZ) n = MAX_COL_NNZ;
    int* a = &g_csc_rows[j * MAX_COL_NNZ];
    for (int k = lane; k < n; k += 32) sh[w][k] = a[k];
    __syncwarp();
    for (int p = 0; p < n; p++) {           // odd-even transposition sort
        int start = p & 1;
        for (int k = start + 2 * lane; k + 1 < n; k += 64) {
            int x = sh[w][k], y = sh[w][k + 1];
            if (x > y) { sh[w][k] = y; sh[w][k + 1] = x; }
        }
        __syncwarp();
    }
    for (int k = lane; k < n; k += 32) a[k] = sh[w][k];
}

// ---------------- K1a: pack/transpose z, lambda1 -> zT, lT, vT ----------------
__global__ void k_pack_zl(const float* __restrict__ z, const float* __restrict__ l,
                          const float* __restrict__ theta) {
    __shared__ float sz[32][33], sl[32][33];
    int i0 = blockIdx.x * 32;   // i (M_A)
    int b0 = blockIdx.y * 32;   // b
    int tx = threadIdx.x, ty = threadIdx.y;
#pragma unroll
    for (int k = 0; k < 32; k += 8) {
        size_t idx = (size_t)(b0 + ty + k) * M_A + (i0 + tx);
        sz[ty + k][tx] = z[idx];
        sl[ty + k][tx] = l[idx];
    }
    __syncthreads();
#pragma unroll
    for (int k = 0; k < 32; k += 8) {
        int i = i0 + ty + k, b = b0 + tx;
        float zv = sz[tx][ty + k], lv = sl[tx][ty + k];
        size_t o = (size_t)i * BATCH + b;
        g_zT[o] = zv;
        g_lT[o] = lv;
        g_vT[o] = theta[i] - zv - lv;
    }
}

// ---------------- generic 32x32 tiled transpose: in(R,C) -> out(C,R) ----------
__global__ void k_transpose(const float* __restrict__ in, float* __restrict__ out,
                            int R, int C) {
    __shared__ float t[32][33];
    int c0 = blockIdx.x * 32, r0 = blockIdx.y * 32;
    int tx = threadIdx.x, ty = threadIdx.y;
#pragma unroll
    for (int k = 0; k < 32; k += 8)
        t[ty + k][tx] = in[(size_t)(r0 + ty + k) * C + (c0 + tx)];
    __syncthreads();
#pragma unroll
    for (int k = 0; k < 32; k += 8)
        out[(size_t)(c0 + ty + k) * R + (r0 + tx)] = t[tx][ty + k];
}

// ---------------- K2: q -> u (column gather over CSC) ----------------
__global__ void __launch_bounds__(BATCH) k_qu(
    const float* __restrict__ lamW, const float* __restrict__ LamA,
    const float* __restrict__ pmiu, const float* __restrict__ palpha) {
    int j = blockIdx.x;
    int b = threadIdx.x;
    __shared__ int sidx[MAX_COL_NNZ];
    __shared__ int scnt;
    if (b == 0) { int c = g_csc_cnt[j]; scnt = (c < MAX_COL_NNZ) ? c : MAX_COL_NNZ; }
    __syncthreads();
    int cnt = scnt;
    for (int k = b; k < cnt; k += BATCH) sidx[k] = g_csc_rows[j * MAX_COL_NNZ + k];
    __syncthreads();

    float s0 = 0.f, s1 = 0.f, s2 = 0.f, s3 = 0.f;
    int k = 0;
    for (; k + 4 <= cnt; k += 4) {
        s0 += g_vT[(size_t)sidx[k    ] * BATCH + b];
        s1 += g_vT[(size_t)sidx[k + 1] * BATCH + b];
        s2 += g_vT[(size_t)sidx[k + 2] * BATCH + b];
        s3 += g_vT[(size_t)sidx[k + 3] * BATCH + b];
    }
    for (; k < cnt; k++) s0 += g_vT[(size_t)sidx[k] * BATCH + b];
    float s = (s0 + s1) + (s2 + s3);

    float miu   = pmiu[0];
    float alpha = palpha[0];
    float lw    = lamW[b];
    float res   = g_FT[(size_t)j * BATCH + b];
    float q = miu * s + 2.0f * lw - TWO_SQ2 * res - alpha;
    float w = 1.0f / (miu * LamA[j] + 4.0f * lw - 2.0f * alpha);
    float uu = q * w;
    uu = fminf(fmaxf(uu, 0.0f), 1.0f);

    g_uT[(size_t)j * BATCH + b] = uu;

    int c = j & 1, t = (j >> 1) & 7, l = j >> 4;
    int m = (c * 8 + t) * LD + l;               // X row-major flat index (r*256+l)
    g_XT[(size_t)m * BATCH + b] = (1.0f - 2.0f * uu) * INV_SQ2;
}

// ---------------- K3: per-batch 16x16 algebra ----------------
__global__ void __launch_bounds__(256) k_batch(
    const float* __restrict__ sigma2I, const float* __restrict__ Y,
    const float* __restrict__ YYp,     const float* __restrict__ realXp,
    const float* __restrict__ imagXp,  const float* __restrict__ lamW,
    const float* __restrict__ pfactor, const float* __restrict__ accin,
    float* __restrict__ outF, float* __restrict__ outLW, float* __restrict__ outAcc) {
    extern __shared__ float sm[];
    float* sXXp = sm;                 // 16*545
    float* sYYp = sXXp + 16 * 545;    // 8*545
    float* sR   = sYYp + 8 * 545;     // 16*33 (augmented [R | I])
    float* sT   = sR + 16 * 33;       // 16*8
    float* sWt  = sT + 128;           // 16*8
    float* sM   = sWt + 128;          // 16*16
    float* sMMt = sM + 256;           // 16*16
    float* sf   = sMMt + 256;         // 16
    __shared__ int   s_piv;
    __shared__ float s_inv;

    int b = blockIdx.x, tid = threadIdx.x;
    const float* gXb = g_X + (size_t)b * LDPC_N;

    // build XXp (16 x 544)
    for (int idx = tid; idx < 16 * 544; idx += 256) {
        int r = idx / 544, col = idx % 544;
        float v;
        if (r < 8) {
            int t = r;
            if      (col < 256) v =  gXb[t * 256 + col];
            else if (col < 272) v =  realXp[b * 128 + t * 16 + (col - 256)];
            else if (col < 528) v =  gXb[(8 + t) * 256 + (col - 272)];
            else                v =  imagXp[b * 128 + t * 16 + (col - 528)];
        } else {
            int t = r - 8;
            if      (col < 256) v = -gXb[(8 + t) * 256 + col];
            else if (col < 272) v = -imagXp[b * 128 + t * 16 + (col - 256)];
            else if (col < 528) v =  gXb[t * 256 + (col - 272)];
            else                v =  realXp[b * 128 + t * 16 + (col - 528)];
        }
        sXXp[r * 545 + col] = v;
    }
    // load YYp[b] (8 x 544)
    for (int idx = tid; idx < 8 * 544; idx += 256) {
        int n = idx / 544, c = idx % 544;
        sYYp[n * 545 + c] = YYp[(size_t)b * (8 * 544) + n * 544 + c];
    }
    __syncthreads();

    // R = XXp @ XXp^T + sigma2_I, augmented with I
    {
        int r1 = tid >> 4, r2 = tid & 15;
        float acc = 0.f;
        for (int c = 0; c < 544; c++) acc += sXXp[r1 * 545 + c] * sXXp[r2 * 545 + c];
        sR[r1 * 33 + r2]      = acc + sigma2I[(size_t)b * 256 + r1 * 16 + r2];
        sR[r1 * 33 + 16 + r2] = (r1 == r2) ? 1.0f : 0.0f;
    }
    __syncthreads();

    // Gauss-Jordan with partial pivoting -> inv(R) in right half
    for (int p = 0; p < 16; p++) {
        if (tid == 0) {
            int piv = p; float best = fabsf(sR[p * 33 + p]);
            for (int r = p + 1; r < 16; r++) {
                float v = fabsf(sR[r * 33 + p]);
                if (v > best) { best = v; piv = r; }
            }
            s_piv = piv;
        }
        __syncthreads();
        if (tid < 32 && s_piv != p) {
            float a = sR[p * 33 + tid];
            sR[p * 33 + tid] = sR[s_piv * 33 + tid];
            sR[s_piv * 33 + tid] = a;
        }
        __syncthreads();
        if (tid == 0) s_inv = 1.0f / sR[p * 33 + p];
        __syncthreads();
        if (tid < 32) sR[p * 33 + tid] *= s_inv;
        __syncthreads();
        if (tid < 16) sf[tid] = sR[tid * 33 + p];
        __syncthreads();
        for (int e = tid; e < 512; e += 256) {
            int r = e >> 5, c = e & 31;
            if (r != p) sR[r * 33 + c] -= sf[r] * sR[p * 33 + c];
        }
        __syncthreads();
    }

    // T = XXp @ YYp^T (16 x 8)
    if (tid < 128) {
        int r = tid >> 3, n = tid & 7;
        float acc = 0.f;
        for (int c = 0; c < 544; c++) acc += sXXp[r * 545 + c] * sYYp[n * 545 + c];
        sT[r * 8 + n] = acc;
    }
    __syncthreads();
    // W_temp = inv_R @ T
    if (tid < 128) {
        int r = tid >> 3, n = tid & 7;
        float acc = 0.f;
#pragma unroll
        for (int k = 0; k < 16; k++) acc += sR[r * 33 + 16 + k] * sT[k * 8 + n];
        sWt[r * 8 + n] = acc;
    }
    __syncthreads();
    // M = WT = [[rW, iW], [-iW, rW]]
    {
        int r = tid >> 4, c = tid & 15;
        int t = r & 7, n = c & 7;
        float v;
        if (r < 8) v = (c < 8) ?  sWt[t * 8 + n]       : sWt[(8 + t) * 8 + n];
        else       v = (c < 8) ? -sWt[(8 + t) * 8 + n] : sWt[t * 8 + n];
        sM[r * 16 + c] = v;
    }
    __syncthreads();
    // MMt = M @ M^T
    {
        int r = tid >> 4, k = tid & 15;
        float acc = 0.f;
#pragma unroll
        for (int m = 0; m < 16; m++) acc += sM[r * 16 + m] * sM[k * 16 + m];
        sMMt[r * 16 + k] = acc;
    }
    __syncthreads();

    float lamN = pfactor[0] * lamW[b];
    if (tid == 0) { outLW[b] = lamN; outAcc[b] = accin[b]; }

    // F_new = M @ Y + lamN * X - MMt @ X    (thread per column l)
    {
        int l = tid;
        float y[16], x[16];
#pragma unroll
        for (int r = 0; r < 16; r++) y[r] = Y[(size_t)b * 4096 + r * 256 + l];
#pragma unroll
        for (int r = 0; r < 8; r++) {
            x[r]     = sXXp[r * 545 + l];          // real_X
            x[8 + r] = sXXp[r * 545 + 272 + l];    // imag_X
        }
#pragma unroll
        for (int r = 0; r < 16; r++) {
            float g = 0.f, h = 0.f;
#pragma unroll
            for (int k = 0; k < 16; k++) {
                g += sM[r * 16 + k]   * y[k];
                h += sMMt[r * 16 + k] * x[k];
            }
            outF[(size_t)b * 4096 + r * 256 + l] = g + lamN * x[r] - h;
        }
    }
}

// ---------------- K4: A@u + z/lambda updates (row gather over CSR) ----------
__global__ void __launch_bounds__(BATCH) k_au(
    const float* __restrict__ theta, const float* __restrict__ prelax,
    const float* __restrict__ pacc) {
    int i = blockIdx.x;
    int b = threadIdx.x;
    __shared__ int sidx[MAX_ROW_NNZ];
    __shared__ int scnt;
    if (b == 0) { int c = g_csr_cnt[i]; scnt = (c < MAX_ROW_NNZ) ? c : MAX_ROW_NNZ; }
    __syncthreads();
    int cnt = scnt;
    for (int k = b; k < cnt; k += BATCH) sidx[k] = g_csr_cols[i * MAX_ROW_NNZ + k];
    __syncthreads();

    float s0 = 0.f, s1 = 0.f;
    int k = 0;
    for (; k + 2 <= cnt; k += 2) {
        s0 += g_uT[(size_t)sidx[k]     * BATCH + b];
        s1 += g_uT[(size_t)sidx[k + 1] * BATCH + b];
    }
    if (k < cnt) s0 += g_uT[(size_t)sidx[k] * BATCH + b];
    float Au = s0 + s1;

    float th = theta[i], relax = prelax[0], acc = pacc[0];
    size_t o = (size_t)i * BATCH + b;
    float zo = g_zT[o], lo = g_lT[o];
    float zt = th - relax * Au - (1.0f - relax) * (th - zo) - lo;
    float zn = fmaxf(zt, 0.0f);
    float ln = zn - zt;                 // = relu(-zt)
    g_zTn[o] = zn + acc * (zn - zo);
    g_lTn[o] = ln + acc * (ln - lo);
}

// ---------------- host launcher ----------------
extern "C" void kernel_launch(void* const* d_in, const int* in_sizes, int n_in,
                              void* d_out, int out_size) {
    const float* sigma2I = (const float*)d_in[0];
    const float* Y       = (const float*)d_in[1];
    const float* YYp     = (const float*)d_in[2];
    const float* realXp  = (const float*)d_in[3];
    const float* imagXp  = (const float*)d_in[4];
    const float* lamW    = (const float*)d_in[5];
    const float* F       = (const float*)d_in[6];
    /* d_in[7] = u (unused by reference) */
    const float* z       = (const float*)d_in[8];
    const float* lam1    = (const float*)d_in[9];
    const float* accnew  = (const float*)d_in[10];
    const float* A       = (const float*)d_in[11];
    const float* theta   = (const float*)d_in[12];
    const float* LamA    = (const float*)d_in[13];
    const float* pmiu    = (const float*)d_in[14];
    const float* palpha  = (const float*)d_in[15];
    const float* pfactor = (const float*)d_in[16];
    const float* prelax  = (const float*)d_in[17];
    const float* pacc    = (const float*)d_in[18];

    float* out   = (float*)d_out;
    float* oLW   = out;                              // 512
    float* oF    = oLW + BATCH;                      // 512*4096
    float* oU    = oF  + (size_t)BATCH * LDPC_N;     // 512*4096
    float* oZ    = oU  + (size_t)BATCH * LDPC_N;     // 512*12288
    float* oL    = oZ  + (size_t)BATCH * M_A;        // 512*12288
    float* oAcc  = oL  + (size_t)BATCH * M_A;        // 512

    // scratch symbol addresses (host API, not a stream op — capture-safe)
    float *pFT, *pUT, *pXT, *pX, *pZTn, *pLTn;
    cudaGetSymbolAddress((void**)&pFT,  g_FT);
    cudaGetSymbolAddress((void**)&pUT,  g_uT);
    cudaGetSymbolAddress((void**)&pXT,  g_XT);
    cudaGetSymbolAddress((void**)&pX,   g_X);
    cudaGetSymbolAddress((void**)&pZTn, g_zTn);
    cudaGetSymbolAddress((void**)&pLTn, g_lTn);

    cudaFuncSetAttribute(k_batch, cudaFuncAttributeMaxDynamicSharedMemorySize,
                         (16 * 545 + 8 * 545 + 16 * 33 + 128 + 128 + 256 + 256 + 16) * 4);

    dim3 t32x8(32, 8);

    // sparse structure rebuild (deterministic)
    k_zero_cnt<<<(LDPC_N + 255) / 256, 256>>>();
    k_build<<<(M_A * 32 + 255) / 256, 256>>>(A);
    k_sort_csc<<<LDPC_N / 8, 256>>>();

    // layout packs
    k_pack_zl<<<dim3(M_A / 32, BATCH / 32), t32x8>>>(z, lam1, theta);
    k_transpose<<<dim3(LDPC_N / 32, BATCH / 32), t32x8>>>(F, pFT, BATCH, LDPC_N);

    // q -> u, X
    k_qu<<<LDPC_N, BATCH>>>(lamW, LamA, pmiu, palpha);

    // uT -> u output; XT -> X (b-major)
    k_transpose<<<dim3(BATCH / 32, LDPC_N / 32), t32x8>>>(pUT, oU, LDPC_N, BATCH);
    k_transpose<<<dim3(BATCH / 32, LDPC_N / 32), t32x8>>>(pXT, pX, LDPC_N, BATCH);

    // per-batch algebra (F_new, lambda_W, acc_new)
    k_batch<<<BATCH, 256,
              (16 * 545 + 8 * 545 + 16 * 33 + 128 + 128 + 256 + 256 + 16) * 4>>>(
        sigma2I, Y, YYp, realXp, imagXp, lamW, pfactor, accnew, oF, oLW, oAcc);

    // A@u and z / lambda1 updates
    k_au<<<M_A, BATCH>>>(theta, prelax, pacc);

    // final transposes to output layout
    k_transpose<<<dim3(BATCH / 32, M_A / 32), t32x8>>>(pZTn, oZ, M_A, BATCH);
    k_transpose<<<dim3(BATCH / 32, M_A / 32), t32x8>>>(pLTn, oL, M_A, BATCH);
}

// round 2
// speedup vs baseline: 1.3046x; 1.3046x over previous
#include <cuda_runtime.h>
#include <cstdint>

// ---------------- problem constants ----------------
#define BATCH   512
#define LD      256
#define LDPC_N  4096
#define M_A     12288
#define MAX_ROW_NNZ 64
#define MAX_COL_NNZ 160

#define TWO_SQ2 2.8284271247461903f
#define INV_SQ2 0.70710678118654752f
#define PX 273

// ---------------- device scratch ----------------
__device__ __align__(16) float g_vT [M_A    * BATCH];   // theta - z - lambda1, (i,b)
__device__ __align__(16) float g_zT [M_A    * BATCH];
__device__ __align__(16) float g_FT [LDPC_N * BATCH];   // F permuted-transposed, (m,b)
__device__ __align__(16) float g_uT [LDPC_N * BATCH];   // u transposed, (j,b)
__device__ __align__(16) float g_XT [LDPC_N * BATCH];   // X transposed, (m,b)
__device__ __align__(16) float g_X  [BATCH * LDPC_N];   // X in (b, 16, 256)

__device__ int g_csr_cols[M_A * MAX_ROW_NNZ];
__device__ int g_csr_cnt [M_A];
__device__ int g_csc_rows[LDPC_N * MAX_COL_NNZ];
__device__ int g_csc_cnt [LDPC_N];

// ---------------- K1: pack z,l -> zT,vT; zero csc counters ----------------
__global__ void k_pack(const float* __restrict__ z, const float* __restrict__ l,
                       const float* __restrict__ theta) {
    __shared__ float sz[32][33], sl[32][33];
    int i0 = blockIdx.x * 32, b0 = blockIdx.y * 32;
    int tx = threadIdx.x, ty = threadIdx.y;
    if (blockIdx.y == 0) {
        int g = blockIdx.x * 256 + ty * 32 + tx;
        if (g < LDPC_N) g_csc_cnt[g] = 0;
    }
#pragma unroll
    for (int k = 0; k < 32; k += 8) {
        size_t idx = (size_t)(b0 + ty + k) * M_A + (i0 + tx);
        sz[ty + k][tx] = z[idx];
        sl[ty + k][tx] = l[idx];
    }
    __syncthreads();
#pragma unroll
    for (int k = 0; k < 32; k += 8) {
        int i = i0 + ty + k, b = b0 + tx;
        float zv = sz[tx][ty + k], lv = sl[tx][ty + k];
        size_t o = (size_t)i * BATCH + b;
        g_zT[o] = zv;
        g_vT[o] = theta[i] - zv - lv;
    }
}

// ---------------- P1: build CSR (ordered, deterministic) + CSC -------------
__global__ void k_build(const float* __restrict__ A) {
    int warp = (blockIdx.x * blockDim.x + threadIdx.x) >> 5;
    int lane = threadIdx.x & 31;
    if (warp >= M_A) return;
    int i = warp;
    const float4* row = (const float4*)(A + (size_t)i * LDPC_N);
    int cnt = 0;
    for (int k0 = 0; k0 < 1024; k0 += 32) {
        float4 v = row[k0 + lane];
#pragma unroll
        for (int c = 0; c < 4; c++) {
            float x = (c == 0) ? v.x : (c == 1) ? v.y : (c == 2) ? v.z : v.w;
            unsigned m = __ballot_sync(0xffffffffu, x != 0.0f);
            if (x != 0.0f) {
                int j = (k0 + lane) * 4 + c;
                int pos = cnt + __popc(m & ((1u << lane) - 1u));
                if (pos < MAX_ROW_NNZ) g_csr_cols[i * MAX_ROW_NNZ + pos] = j;
                int cp = atomicAdd(&g_csc_cnt[j], 1);
                if (cp < MAX_COL_NNZ) g_csc_rows[j * MAX_COL_NNZ + cp] = i;
            }
            cnt += __popc(m);
        }
    }
    if (lane == 0) g_csr_cnt[i] = (cnt < MAX_ROW_NNZ) ? cnt : MAX_ROW_NNZ;
}

// ---------------- P2: sort each CSC column (determinism) ----------------
__global__ void k_sort_csc() {
    int w    = threadIdx.x >> 5;
    int lane = threadIdx.x & 31;
    int j    = blockIdx.x * 8 + w;
    if (j >= LDPC_N) return;
    __shared__ int sh[8][MAX_COL_NNZ];
    int n = g_csc_cnt[j];
    if (n > MAX_COL_NNZ) n = MAX_COL_NNZ;
    int* a = &g_csc_rows[j * MAX_COL_NNZ];
    for (int k = lane; k < n; k += 32) sh[w][k] = a[k];
    __syncwarp();
    for (int p = 0; p < n; p++) {
        int start = p & 1;
        for (int k = start + 2 * lane; k + 1 < n; k += 64) {
            int x = sh[w][k], y = sh[w][k + 1];
            if (x > y) { sh[w][k] = y; sh[w][k + 1] = x; }
        }
        __syncwarp();
    }
    for (int k = lane; k < n; k += 32) a[k] = sh[w][k];
}

// ---------------- generic 32x32 tiled transpose ----------------
__global__ void k_transpose(const float* __restrict__ in, float* __restrict__ out,
                            int R, int C) {
    __shared__ float t[32][33];
    int c0 = blockIdx.x * 32, r0 = blockIdx.y * 32;
    int tx = threadIdx.x, ty = threadIdx.y;
#pragma unroll
    for (int k = 0; k < 32; k += 8)
        t[ty + k][tx] = in[(size_t)(r0 + ty + k) * C + (c0 + tx)];
    __syncthreads();
#pragma unroll
    for (int k = 0; k < 32; k += 8)
        out[(size_t)(c0 + ty + k) * R + (r0 + tx)] = t[tx][ty + k];
}

// dual transpose: z-index selects uT->oU or XT->gX (both 4096x512 -> 512x4096)
__global__ void k_dual_t(float* __restrict__ oU, float* __restrict__ gX) {
    __shared__ float t[32][33];
    const float* in = (blockIdx.z == 0) ? g_uT : g_XT;
    float* out      = (blockIdx.z == 0) ? oU   : gX;
    int c0 = blockIdx.x * 32, r0 = blockIdx.y * 32;   // c over BATCH, r over LDPC_N
    int tx = threadIdx.x, ty = threadIdx.y;
#pragma unroll
    for (int k = 0; k < 32; k += 8)
        t[ty + k][tx] = in[(size_t)(r0 + ty + k) * BATCH + (c0 + tx)];
    __syncthreads();
#pragma unroll
    for (int k = 0; k < 32; k += 8)
        out[(size_t)(c0 + ty + k) * LDPC_N + (r0 + tx)] = t[tx][ty + k];
}

// ---------------- K2: q -> u (CSC gather, float4 over batch) ----------------
__global__ void __launch_bounds__(128) k_qu(
    const float* __restrict__ lamW, const float* __restrict__ LamA,
    const float* __restrict__ pmiu, const float* __restrict__ palpha) {
    int j  = blockIdx.x;
    int tx = threadIdx.x;
    __shared__ int sidx[MAX_COL_NNZ];
    __shared__ int scnt;
    if (tx == 0) { int c = g_csc_cnt[j]; scnt = (c < MAX_COL_NNZ) ? c : MAX_COL_NNZ; }
    __syncthreads();
    int cnt = scnt;
    for (int k = tx; k < cnt; k += 128) sidx[k] = g_csc_rows[j * MAX_COL_NNZ + k];
    __syncthreads();

    const float4* vT4 = (const float4*)g_vT;
    float4 s0 = make_float4(0.f, 0.f, 0.f, 0.f);
    float4 s1 = make_float4(0.f, 0.f, 0.f, 0.f);
    int k = 0;
    for (; k + 2 <= cnt; k += 2) {
        float4 x = vT4[(size_t)sidx[k]     * 128 + tx];
        float4 y = vT4[(size_t)sidx[k + 1] * 128 + tx];
        s0.x += x.x; s0.y += x.y; s0.z += x.z; s0.w += x.w;
        s1.x += y.x; s1.y += y.y; s1.z += y.z; s1.w += y.w;
    }
    if (k < cnt) {
        float4 x = vT4[(size_t)sidx[k] * 128 + tx];
        s0.x += x.x; s0.y += x.y; s0.z += x.z; s0.w += x.w;
    }
    float4 s = make_float4(s0.x + s1.x, s0.y + s1.y, s0.z + s1.z, s0.w + s1.w);

    int c = j & 1, t = (j >> 1) & 7, l = j >> 4;
    int m = (c * 8 + t) * LD + l;                     // F/X permuted index

    float4 res = ((const float4*)g_FT)[(size_t)m * 128 + tx];
    float4 lw  = ((const float4*)lamW)[tx];
    float miu = pmiu[0], alpha = palpha[0];
    float mlam = miu * LamA[j];

    float4 uu;
    {
        float q0 = miu * s.x + 2.f * lw.x - TWO_SQ2 * res.x - alpha;
        float q1 = miu * s.y + 2.f * lw.y - TWO_SQ2 * res.y - alpha;
        float q2 = miu * s.z + 2.f * lw.z - TWO_SQ2 * res.z - alpha;
        float q3 = miu * s.w + 2.f * lw.w - TWO_SQ2 * res.w - alpha;
        uu.x = fminf(fmaxf(q0 / (mlam + 4.f * lw.x - 2.f * alpha), 0.f), 1.f);
        uu.y = fminf(fmaxf(q1 / (mlam + 4.f * lw.y - 2.f * alpha), 0.f), 1.f);
        uu.z = fminf(fmaxf(q2 / (mlam + 4.f * lw.z - 2.f * alpha), 0.f), 1.f);
        uu.w = fminf(fmaxf(q3 / (mlam + 4.f * lw.w - 2.f * alpha), 0.f), 1.f);
    }
    ((float4*)g_uT)[(size_t)j * 128 + tx] = uu;
    float4 xx;
    xx.x = (1.f - 2.f * uu.x) * INV_SQ2;
    xx.y = (1.f - 2.f * uu.y) * INV_SQ2;
    xx.z = (1.f - 2.f * uu.z) * INV_SQ2;
    xx.w = (1.f - 2.f * uu.w) * INV_SQ2;
    ((float4*)g_XT)[(size_t)m * 128 + tx] = xx;
}

// ---------------- K3: per-batch 16x16 algebra (structured) ----------------
__global__ void __launch_bounds__(256) k_batch(
    const float* __restrict__ sigma2I, const float* __restrict__ Y,
    const float* __restrict__ YYp,     const float* __restrict__ realXp,
    const float* __restrict__ imagXp,  const float* __restrict__ lamW,
    const float* __restrict__ pfactor, const float* __restrict__ accin,
    float* __restrict__ outF, float* __restrict__ outLW, float* __restrict__ outAcc) {
    extern __shared__ float sm[];
    float* sa   = sm;                 // 8 x PX (real XXp half)
    float* sb   = sa  + 8 * PX;       // 8 x PX (imag XXp half)
    float* sY1  = sb  + 8 * PX;       // 8 x PX
    float* sY2  = sY1 + 8 * PX;       // 8 x PX
    float* sR   = sY2 + 8 * PX;       // 16 x 33 (augmented [R|inv])
    float* pA   = sR  + 16 * 33;      // 1024 partials (reused)
    float* sT   = pA  + 1024;         // 16 x 8
    float* sM   = sT  + 128;          // 16 x 16
    float* sMMt = sM  + 256;          // 16 x 16

    int b = blockIdx.x, tid = threadIdx.x;
    const float* gXb = g_X + (size_t)b * LDPC_N;

    // load a, b (8 x 272 each)
    for (int idx = tid; idx < 8 * 272; idx += 256) {
        int t = idx / 272, c = idx % 272;
        float av, bv;
        if (c < 256) { av = gXb[t * 256 + c]; bv = gXb[(8 + t) * 256 + c]; }
        else {
            av = realXp[b * 128 + t * 16 + (c - 256)];
            bv = imagXp[b * 128 + t * 16 + (c - 256)];
        }
        sa[t * PX + c] = av;
        sb[t * PX + c] = bv;
    }
    // load YYp halves
    for (int idx = tid; idx < 8 * 544; idx += 256) {
        int n = idx / 544, c = idx % 544;
        float v = YYp[(size_t)b * (8 * 544) + n * 544 + c];
        if (c < 272) sY1[n * PX + c] = v;
        else         sY2[n * PX + (c - 272)] = v;
    }
    __syncthreads();

    // Gram partials: pair=(r1,r2) in 8x8, chunk splits 272 into 4x68
    {
        int pair = tid & 63; int r1 = pair >> 3, r2 = pair & 7;
        int chunk = tid >> 6;
        int cbeg = chunk * 68;
        float saa = 0.f, sbb = 0.f, sab = 0.f, sba = 0.f;
#pragma unroll 4
        for (int c = cbeg; c < cbeg + 68; c++) {
            float a1 = sa[r1 * PX + c], a2 = sa[r2 * PX + c];
            float b1 = sb[r1 * PX + c], b2 = sb[r2 * PX + c];
            saa += a1 * a2; sbb += b1 * b2; sab += a1 * b2; sba += b1 * a2;
        }
        pA[tid] = saa; pA[256 + tid] = sbb; pA[512 + tid] = sab; pA[768 + tid] = sba;
    }
    __syncthreads();

    // assemble R (16x16) + sigma2I, augmented with I
    {
        int r = tid >> 4, c = tid & 15;
        int rr = r & 7, cc = c & 7;
        int pair = rr * 8 + cc;
        float S = 0.f, G2 = 0.f;
#pragma unroll
        for (int ch = 0; ch < 4; ch++) {
            float aa = pA[ch * 64 + pair],       bb = pA[256 + ch * 64 + pair];
            float ab = pA[512 + ch * 64 + pair], ba = pA[768 + ch * 64 + pair];
            S += aa + bb; G2 += ba - ab;
        }
        float v;
        if (r < 8) v = (c < 8) ?  S  : G2;
        else       v = (c < 8) ? -G2 : S;
        sR[r * 33 + c]      = v + sigma2I[(size_t)b * 256 + r * 16 + c];
        sR[r * 33 + 16 + c] = (r == c) ? 1.0f : 0.0f;
    }
    __syncthreads();

    // warp 0: Gauss-Jordan inverse (SPD, no pivoting), columns in lanes.
    // warps 1..7: T = XXp @ YYp^T partials in parallel.
    if (tid < 32) {
        float rr_[16];
#pragma unroll
        for (int i = 0; i < 16; i++) rr_[i] = sR[i * 33 + tid];
#pragma unroll
        for (int p = 0; p < 16; p++) {
            float piv = __shfl_sync(0xffffffffu, rr_[p], p);
            float pinv = 1.0f / piv;
            rr_[p] *= pinv;
#pragma unroll
            for (int i = 0; i < 16; i++) {
                if (i == p) continue;
                float f = __shfl_sync(0xffffffffu, rr_[i], p);
                rr_[i] -= f * rr_[p];
            }
        }
        if (tid >= 16) {
#pragma unroll
            for (int i = 0; i < 16; i++) sR[i * 33 + 16 + (tid - 16)] = rr_[i];
        }
    } else {
        int t2 = tid - 32;
        int pair = t2 & 63;
        int r = pair >> 3, n = pair & 7;
        int chunk = t2 >> 6;                 // 0..3, only 0..2 work
        if (chunk < 3) {
            int cbeg = chunk * 91;
            int cend = (cbeg + 91 < 272) ? cbeg + 91 : 272;
            float s1 = 0.f, s2 = 0.f, s3 = 0.f, s4 = 0.f;
            for (int c = cbeg; c < cend; c++) {
                float av = sa[r * PX + c], bv = sb[r * PX + c];
                float y1 = sY1[n * PX + c], y2 = sY2[n * PX + c];
                s1 += av * y1; s2 += bv * y2; s3 += bv * y1; s4 += av * y2;
            }
            pA[      chunk * 64 + pair] = s1;
            pA[192 + chunk * 64 + pair] = s2;
            pA[384 + chunk * 64 + pair] = s3;
            pA[576 + chunk * 64 + pair] = s4;
        }
    }
    __syncthreads();

    // reduce T (16 x 8)
    if (tid < 128) {
        int r = tid >> 3, n = tid & 7;
        int rr = r & 7;
        int pair = rr * 8 + n;
        float acc = 0.f;
#pragma unroll
        for (int ch = 0; ch < 3; ch++) {
            if (r < 8) acc += pA[ch * 64 + pair] + pA[192 + ch * 64 + pair];
            else       acc += pA[576 + ch * 64 + pair] - pA[384 + ch * 64 + pair];
        }
        sT[r * 8 + n] = acc;
    }
    __syncthreads();

    // W_temp = invR @ T, scattered directly into M = [[rW,iW],[-iW,rW]]
    if (tid < 128) {
        int r = tid >> 3, n = tid & 7;
        float acc = 0.f;
#pragma unroll
        for (int k2 = 0; k2 < 16; k2++) acc += sR[r * 33 + 16 + k2] * sT[k2 * 8 + n];
        if (r < 8) { sM[r * 16 + n] = acc; sM[(8 + r) * 16 + (8 + n)] = acc; }
        else       { sM[(r - 8) * 16 + (8 + n)] = acc; sM[r * 16 + n] = -acc; }
    }
    __syncthreads();

    // MMt = M @ M^T
    {
        int r = tid >> 4, k2 = tid & 15;
        float acc = 0.f;
#pragma unroll
        for (int m = 0; m < 16; m++) acc += sM[r * 16 + m] * sM[k2 * 16 + m];
        sMMt[r * 16 + k2] = acc;
    }
    __syncthreads();

    float lamN = pfactor[0] * lamW[b];
    if (tid == 0) { outLW[b] = lamN; outAcc[b] = accin[b]; }

    // F_new = M @ Y + lamN * X - MMt @ X   (thread per column l)
    {
        int l = tid;
        float y[16], x[16];
#pragma unroll
        for (int r = 0; r < 16; r++) y[r] = Y[(size_t)b * 4096 + r * 256 + l];
#pragma unroll
        for (int r = 0; r < 8; r++) {
            x[r]     = sa[r * PX + l];
            x[8 + r] = sb[r * PX + l];
        }
#pragma unroll
        for (int r = 0; r < 16; r++) {
            float g = 0.f, h = 0.f;
#pragma unroll
            for (int k2 = 0; k2 < 16; k2++) {
                g += sM[r * 16 + k2]   * y[k2];
                h += sMMt[r * 16 + k2] * x[k2];
            }
            outF[(size_t)b * 4096 + r * 256 + l] = g + lamN * x[r] - h;
        }
    }
}

// ---------------- K4: A@u + z/lambda updates, fused transpose out ----------
__global__ void __launch_bounds__(256) k_au_t(
    const float* __restrict__ theta, const float* __restrict__ prelax,
    const float* __restrict__ pacc,
    float* __restrict__ oZ, float* __restrict__ oL) {
    __shared__ int   sidx[32][MAX_ROW_NNZ];
    __shared__ int   scnt[32];
    __shared__ float tz[32][33], tl[32][33];
    int i0 = blockIdx.x * 32, b0 = blockIdx.y * 32;
    int tx = threadIdx.x, ty = threadIdx.y;          // (32, 8)
    int tid = ty * 32 + tx;
    if (tid < 32) {
        int c = g_csr_cnt[i0 + tid];
        scnt[tid] = (c < MAX_ROW_NNZ) ? c : MAX_ROW_NNZ;
    }
    __syncthreads();
    for (int r = ty; r < 32; r += 8)
        for (int k = tx; k < scnt[r]; k += 32)
            sidx[r][k] = g_csr_cols[(i0 + r) * MAX_ROW_NNZ + k];
    __syncthreads();

    float relax = prelax[0], acc = pacc[0];
#pragma unroll
    for (int kk = 0; kk < 4; kk++) {
        int il = ty + 8 * kk;
        int i  = i0 + il;
        int cnt = scnt[il];
        const int* idx = sidx[il];
        float s0 = 0.f, s1 = 0.f;
        int k = 0;
        for (; k + 2 <= cnt; k += 2) {
            s0 += g_uT[(size_t)idx[k]     * BATCH + b0 + tx];
            s1 += g_uT[(size_t)idx[k + 1] * BATCH + b0 + tx];
        }
        if (k < cnt) s0 += g_uT[(size_t)idx[k] * BATCH + b0 + tx];
        float Au = s0 + s1;

        size_t o = (size_t)i * BATCH + b0 + tx;
        float zo = g_zT[o], v = g_vT[o];
        float th = theta[i];
        float lo = th - zo - v;
        float zt = th - relax * Au - (1.0f - relax) * (th - zo) - lo;
        float zn = fmaxf(zt, 0.0f);
        float ln = zn - zt;
        tz[il][tx] = zn + acc * (zn - zo);
        tl[il][tx] = ln + acc * (ln - lo);
    }
    __syncthreads();
#pragma unroll
    for (int kk = 0; kk < 4; kk++) {
        int bl = ty + 8 * kk;
        size_t o = (size_t)(b0 + bl) * M_A + i0 + tx;
        oZ[o] = tz[tx][bl];
        oL[o] = tl[tx][bl];
    }
}

// ---------------- host launcher ----------------
extern "C" void kernel_launch(void* const* d_in, const int* in_sizes, int n_in,
                              void* d_out, int out_size) {
    const float* sigma2I = (const float*)d_in[0];
    const float* Y       = (const float*)d_in[1];
    const float* YYp     = (const float*)d_in[2];
    const float* realXp  = (const float*)d_in[3];
    const float* imagXp  = (const float*)d_in[4];
    const float* lamW    = (const float*)d_in[5];
    const float* F       = (const float*)d_in[6];
    const float* z       = (const float*)d_in[8];
    const float* lam1    = (const float*)d_in[9];
    const float* accnew  = (const float*)d_in[10];
    const float* A       = (const float*)d_in[11];
    const float* theta   = (const float*)d_in[12];
    const float* LamA    = (const float*)d_in[13];
    const float* pmiu    = (const float*)d_in[14];
    const float* palpha  = (const float*)d_in[15];
    const float* pfactor = (const float*)d_in[16];
    const float* prelax  = (const float*)d_in[17];
    const float* pacc    = (const float*)d_in[18];

    float* out   = (float*)d_out;
    float* oLW   = out;                              // 512
    float* oF    = oLW + BATCH;                      // 512*4096
    float* oU    = oF  + (size_t)BATCH * LDPC_N;     // 512*4096
    float* oZ    = oU  + (size_t)BATCH * LDPC_N;     // 512*12288
    float* oL    = oZ  + (size_t)BATCH * M_A;        // 512*12288
    float* oAcc  = oL  + (size_t)BATCH * M_A;        // 512

    float *pFT, *pX;
    cudaGetSymbolAddress((void**)&pFT, g_FT);
    cudaGetSymbolAddress((void**)&pX,  g_X);

    const int SMEM_BATCH = (4 * 8 * PX + 16 * 33 + 1024 + 128 + 256 + 256) * 4;
    cudaFuncSetAttribute(k_batch, cudaFuncAttributeMaxDynamicSharedMemorySize, SMEM_BATCH);

    dim3 t32x8(32, 8);

    // pack (also zeroes csc counters), then structure rebuild
    k_pack<<<dim3(M_A / 32, BATCH / 32), t32x8>>>(z, lam1, theta);
    k_build<<<(M_A * 32 + 255) / 256, 256>>>(A);
    k_sort_csc<<<LDPC_N / 8, 256>>>();

    // F -> FT (natural m-order transpose; k_qu indexes by permuted m)
    k_transpose<<<dim3(LDPC_N / 32, BATCH / 32), t32x8>>>(F, pFT, BATCH, LDPC_N);

    // q -> u, X
    k_qu<<<LDPC_N, 128>>>(lamW, LamA, pmiu, palpha);

    // uT -> oU  and  XT -> g_X in one launch
    k_dual_t<<<dim3(BATCH / 32, LDPC_N / 32, 2), t32x8>>>(oU, pX);

    // per-batch algebra
    k_batch<<<BATCH, 256, SMEM_BATCH>>>(
        sigma2I, Y, YYp, realXp, imagXp, lamW, pfactor, accnew, oF, oLW, oAcc);

    // A@u, z/lambda updates, transposed output
    k_au_t<<<dim3(M_A / 32, BATCH / 32), t32x8>>>(theta, prelax, pacc, oZ, oL);
}